// round 7
// baseline (speedup 1.0000x reference)
#include <cuda_runtime.h>
#include <cstdint>

#define B_ 64
#define N_ 25
#define C_ 128
#define T_ 256

// ---------------- device scratch ----------------
__device__ float g_xm[B_ * N_ * C_ * T_];      // node-mixed x: [b][m][c][t]
__device__ float g_Bf[3 * 4 * 4 * 2 * 4 * 32 * 4]; // Weff frag order [k][cc][ks][half][wn][lane][4]
__device__ float g_WcT[3 * 128 * 128];         // Wc transposed: [k][i][o]
__device__ float g_sfull[C_], g_s0[C_], g_sT[C_];
__device__ float g_tcs[C_], g_tcb[C_], g_bns[C_], g_bnb[C_], g_bconv[C_];
__device__ float g_rowsum[N_];

__device__ __forceinline__ uint32_t f2tf32(float f) {
    uint32_t r;
    asm("cvt.rna.tf32.f32 %0, %1;" : "=r"(r) : "f"(f));
    return r;
}

__device__ __forceinline__ void mma_tf32(float* d, const uint32_t* a, uint32_t b0, uint32_t b1) {
    asm volatile(
        "mma.sync.aligned.m16n8k8.row.col.f32.tf32.tf32.f32 "
        "{%0,%1,%2,%3}, {%4,%5,%6,%7}, {%8,%9}, {%0,%1,%2,%3};"
        : "+f"(d[0]), "+f"(d[1]), "+f"(d[2]), "+f"(d[3])
        : "r"(a[0]), "r"(a[1]), "r"(a[2]), "r"(a[3]), "r"(b0), "r"(b1));
}

// ---------------- precompute stage 1: transpose Wc [o][i][k] -> [k][i][o] ----------------
__global__ void transpose_wc_kernel(const float* __restrict__ Wc)
{
    int idx = blockIdx.x * 256 + threadIdx.x;   // 3*128*128 = 49152
    if (idx < 3 * 128 * 128) {
        int o = idx & 127, i = (idx >> 7) & 127, k = idx >> 14;
        g_WcT[idx] = Wc[(o * 128 + i) * 3 + k];  // write coalesced (o fastest)
    }
}

// ---------------- precompute stage 2: Weff[k][c][o] -> fragment layout g_Bf ----------------
// B frag mapping (from verified R3 addressing): for chunk c-index c = cc*32 + 8*ks + q,
// mma K-lane = q&3 + 4*j; o = wn*32 + 8*nt + (lane>>2).
__global__ void precompute_w_kernel(const float* __restrict__ Wg)
{
    int k = blockIdx.x >> 3;
    int c0 = (blockIdx.x & 7) * 16;
    int o = threadIdx.x;  // 128 threads
    __shared__ float wgs[128][17];
    #pragma unroll
    for (int e = 0; e < 16; e++) {
        int idx = o + 128 * e;          // 0..2047
        int i = idx >> 4, j = idx & 15;
        wgs[i][j] = Wg[i * 128 + c0 + j];
    }
    __syncthreads();
    float acc[16];
    #pragma unroll
    for (int j = 0; j < 16; j++) acc[j] = 0.f;
    const float* wt = g_WcT + k * 16384 + o;
    #pragma unroll 4
    for (int i = 0; i < 128; i++) {
        float w = wt[i * 128];
        #pragma unroll
        for (int j = 0; j < 16; j++) acc[j] += w * wgs[i][j];
    }
    int wn = o >> 5, s = o & 31;
    int l2 = s & 7, nt = s >> 3, half = nt >> 1, ntl = nt & 1;
    #pragma unroll
    for (int jj = 0; jj < 16; jj++) {
        int c = c0 + jj;
        int cc = c >> 5, r = c & 31;
        int ks = r >> 3, q = r & 7;
        int lj = q & 3, j = q >> 2;
        int lane = (l2 << 2) | lj;
        int j4 = (ntl << 1) | j;
        size_t idx = ((size_t)(((((k * 4 + cc) * 4 + ks) * 2 + half) * 4 + wn) * 32 + lane) << 2) + j4;
        g_Bf[idx] = __uint_as_float(f2tf32(acc[jj]));
    }
}

// ---------------- precompute stage 3: biases / BN folds / adj row sums ----------------
__global__ void precompute_bias_kernel(
    const float* __restrict__ bg, const float* __restrict__ Wc,
    const float* __restrict__ bc,
    const float* __restrict__ tg, const float* __restrict__ tb,
    const float* __restrict__ tm, const float* __restrict__ tv,
    const float* __restrict__ bng, const float* __restrict__ bnbt,
    const float* __restrict__ bnm, const float* __restrict__ bnv,
    const float* __restrict__ adj)
{
    int o = threadIdx.x;  // 128
    float s0 = 0.f, s1 = 0.f, s2 = 0.f;
    for (int i = 0; i < C_; i++) {
        float b = bg[i];
        const float* w = &Wc[(o * C_ + i) * 3];
        s0 += w[0] * b; s1 += w[1] * b; s2 += w[2] * b;
    }
    g_sfull[o] = s0 + s1 + s2;
    g_s0[o] = s1 + s2;     // t==0: window misses k=0
    g_sT[o] = s0 + s1;     // t==T-1: window misses k=2
    g_bconv[o] = bc[o];
    float ts = tg[o] * rsqrtf(tv[o] + 1e-5f);
    g_tcs[o] = ts; g_tcb[o] = tb[o] - tm[o] * ts;
    float bs = bng[o] * rsqrtf(bnv[o] + 1e-5f);
    g_bns[o] = bs; g_bnb[o] = bnbt[o] - bnm[o] * bs;
    if (o < N_) {
        float r = 0.f;
        for (int n = 0; n < N_; n++) r += adj[o * N_ + n];
        g_rowsum[o] = r;
    }
}

// ---------------- kernel 2: node mix  xm[b,m,c,t] = sum_n adj[m,n] x[b,n,c,t] ----------------
__global__ __launch_bounds__(256) void mix_kernel(const float* __restrict__ x,
                                                  const float* __restrict__ adj)
{
    __shared__ float adjs[N_ * N_];
    int tid = threadIdx.x;
    for (int i = tid; i < N_ * N_; i += 256) adjs[i] = adj[i];
    __syncthreads();

    int b = blockIdx.y;
    int pos = blockIdx.x * 256 + tid;  // float4 index in [0, C*T/4)
    const float4* xb = (const float4*)x + (size_t)b * N_ * (C_ * T_ / 4) + pos;
    float4* xmb = (float4*)g_xm + (size_t)b * N_ * (C_ * T_ / 4) + pos;

    float4 acc[N_];
    #pragma unroll
    for (int m = 0; m < N_; m++) acc[m] = make_float4(0.f, 0.f, 0.f, 0.f);

    #pragma unroll 1
    for (int n = 0; n < N_; n++) {
        float4 v = xb[n * (C_ * T_ / 4)];
        #pragma unroll
        for (int m = 0; m < N_; m++) {
            float a = adjs[m * N_ + n];
            acc[m].x += a * v.x; acc[m].y += a * v.y;
            acc[m].z += a * v.z; acc[m].w += a * v.w;
        }
    }
    #pragma unroll
    for (int m = 0; m < N_; m++) xmb[m * (C_ * T_ / 4)] = acc[m];
}

// ---------------- kernel 3: tf32 mma.sync conv-GEMM + full epilogue ----------------
// y[o, t] = sum_{k,c} Weff[k][c][o] * xm[c, t+k-1]   (M=128 t, N=128 o, K=384)
// B (Weff) lives in SMEM in mma-fragment order: 2 conflict-free LDS.128 per ks-step.
#define XS_STRIDE 136
#define BW_FLOATS (3 * 4 * 4 * 2 * 4 * 32 * 4)          // 49152 floats = 192 KB
#define GEMM_SMEM (BW_FLOATS * 4 + 64 * 130 * 4)        // 196608 + 33280 = 229888 B

__global__ __launch_bounds__(256) void stgemm_kernel(const float* __restrict__ x,
                                                     float* __restrict__ out)
{
    extern __shared__ float smemf[];
    float4* Bw4 = (float4*)smemf;                 // fragment-ordered Weff, 12288 float4
    float* xs = smemf + BW_FLOATS;                // [32][136] staging
    float* Ds = smemf + BW_FLOATS;                // [64][130] epilogue (aliases xs)

    int tid = threadIdx.x, lane = tid & 31, wid = tid >> 5;
    int wm = wid >> 2, wn = wid & 3;
    int t0 = blockIdx.x * 128;
    int m_node = blockIdx.y;
    int node = blockIdx.z * N_ + m_node;
    const float* xp = g_xm + (size_t)node * C_ * T_;

    // one-time copy of fragment-ordered Weff into smem (coalesced LDG.128 + STS.128)
    {
        const float4* src = (const float4*)g_Bf;
        #pragma unroll
        for (int i = 0; i < 48; i++) Bw4[tid + 256 * i] = src[tid + 256 * i];
    }

    float d[4][4][4];
    #pragma unroll
    for (int mt = 0; mt < 4; mt++)
        #pragma unroll
        for (int nt = 0; nt < 4; nt++)
            #pragma unroll
            for (int r = 0; r < 4; r++) d[mt][nt][r] = 0.f;

    const float* xsb = xs + (lane & 3) * XS_STRIDE + wm * 64 + (lane >> 2) + 3;

    #pragma unroll 1
    for (int cc = 0; cc < 4; cc++) {
        int c0 = cc * 32;
        __syncthreads();
        // stage xm rows [c0..c0+32) x t window [t0-1, t0+128], tf32-rounded
        #pragma unroll
        for (int e = 0; e < 4; e++) {
            int idx = tid + 256 * e;               // 0..1023
            int ci = idx >> 5, tq = idx & 31;
            float4 v = *(const float4*)&xp[(c0 + ci) * T_ + t0 + 4 * tq];
            v.x = __uint_as_float(f2tf32(v.x));
            v.y = __uint_as_float(f2tf32(v.y));
            v.z = __uint_as_float(f2tf32(v.z));
            v.w = __uint_as_float(f2tf32(v.w));
            *(float4*)&xs[ci * XS_STRIDE + 4 + 4 * tq] = v;
        }
        if (tid < 32) {
            xs[tid * XS_STRIDE + 3] =
                (t0 > 0) ? __uint_as_float(f2tf32(xp[(c0 + tid) * T_ + t0 - 1])) : 0.f;
        } else if (tid < 64) {
            int ci = tid - 32;
            xs[ci * XS_STRIDE + 132] =
                (t0 + 128 < T_) ? __uint_as_float(f2tf32(xp[(c0 + ci) * T_ + t0 + 128])) : 0.f;
        }
        __syncthreads();

        #pragma unroll 1
        for (int k = 0; k < 3; k++) {
            #pragma unroll
            for (int ks = 0; ks < 4; ks++) {
                // B frags: two conflict-free LDS.128 from fragment-ordered smem
                int fb = ((k * 4 + cc) * 4 + ks) * 2;
                float4 v0 = Bw4[((fb + 0) * 4 + wn) * 32 + lane];
                float4 v1 = Bw4[((fb + 1) * 4 + wn) * 32 + lane];
                uint32_t bb[8];
                bb[0] = __float_as_uint(v0.x); bb[1] = __float_as_uint(v0.y);
                bb[2] = __float_as_uint(v0.z); bb[3] = __float_as_uint(v0.w);
                bb[4] = __float_as_uint(v1.x); bb[5] = __float_as_uint(v1.y);
                bb[6] = __float_as_uint(v1.z); bb[7] = __float_as_uint(v1.w);

                const float* xq = xsb + 8 * ks * XS_STRIDE + k;
                #pragma unroll
                for (int mt = 0; mt < 4; mt++) {
                    uint32_t a[4];
                    a[0] = __float_as_uint(xq[mt * 16]);
                    a[1] = __float_as_uint(xq[mt * 16 + 8]);
                    a[2] = __float_as_uint(xq[4 * XS_STRIDE + mt * 16]);
                    a[3] = __float_as_uint(xq[4 * XS_STRIDE + mt * 16 + 8]);
                    #pragma unroll
                    for (int nt = 0; nt < 4; nt++)
                        mma_tf32(d[mt][nt], a, bb[2 * nt], bb[2 * nt + 1]);
                }
            }
        }
    }

    // ---- epilogue: transpose through smem + bias/BN/relu/residual, coalesced out ----
    const float* xr = x + (size_t)node * C_ * T_;
    float* yo = out + (size_t)node * C_ * T_;
    float rs = g_rowsum[m_node];

    #pragma unroll 1
    for (int p = 0; p < 2; p++) {
        __syncthreads();
        if (wm == p) {
            #pragma unroll
            for (int mt = 0; mt < 4; mt++) {
                int r = mt * 16 + (lane >> 2);
                #pragma unroll
                for (int nt = 0; nt < 4; nt++) {
                    int cl = wn * 32 + nt * 8 + 2 * (lane & 3);
                    *(float2*)&Ds[r * 130 + cl]       = make_float2(d[mt][nt][0], d[mt][nt][1]);
                    *(float2*)&Ds[(r + 8) * 130 + cl] = make_float2(d[mt][nt][2], d[mt][nt][3]);
                }
            }
        }
        __syncthreads();
        #pragma unroll
        for (int i = 0; i < 32; i++) {
            int idx = tid + 256 * i;       // 0..8191
            int o = idx >> 6, tt = idx & 63;
            int t = t0 + p * 64 + tt;
            float v = Ds[tt * 130 + o];
            float sv = g_sfull[o];
            if (t == 0) sv = g_s0[o];
            else if (t == T_ - 1) sv = g_sT[o];
            float bias = g_bconv[o] + rs * sv;
            float p1 = v + bias;
            float y1 = fmaxf(g_tcs[o] * p1 + g_tcb[o], 0.f);
            float y2 = y1 + xr[o * T_ + t];
            yo[o * T_ + t] = fmaxf(g_bns[o] * y2 + g_bnb[o], 0.f);
        }
    }
}

// ---------------- launch ----------------
extern "C" void kernel_launch(void* const* d_in, const int* in_sizes, int n_in,
                              void* d_out, int out_size)
{
    const float* x   = (const float*)d_in[0];
    const float* adj = (const float*)d_in[1];
    const float* Wg  = (const float*)d_in[2];
    const float* bg  = (const float*)d_in[3];
    const float* Wc  = (const float*)d_in[4];
    const float* bc  = (const float*)d_in[5];
    const float* tg  = (const float*)d_in[6];
    const float* tb  = (const float*)d_in[7];
    const float* tm  = (const float*)d_in[8];
    const float* tv  = (const float*)d_in[9];
    const float* bng = (const float*)d_in[10];
    const float* bnb = (const float*)d_in[11];
    const float* bnm = (const float*)d_in[12];
    const float* bnv = (const float*)d_in[13];

    cudaFuncSetAttribute(stgemm_kernel, cudaFuncAttributeMaxDynamicSharedMemorySize, GEMM_SMEM);

    transpose_wc_kernel<<<192, 256>>>(Wc);
    precompute_w_kernel<<<24, 128>>>(Wg);
    precompute_bias_kernel<<<1, 128>>>(bg, Wc, bc, tg, tb, tm, tv, bng, bnb, bnm, bnv, adj);
    mix_kernel<<<dim3(C_ * T_ / 4 / 256, B_), 256>>>(x, adj);
    stgemm_kernel<<<dim3(2, N_, B_), 256, GEMM_SMEM>>>(x, (float*)d_out);
}

// round 8
// speedup vs baseline: 1.0088x; 1.0088x over previous
#include <cuda_runtime.h>
#include <cstdint>

#define B_ 64
#define N_ 25
#define C_ 128
#define T_ 256

// ---------------- device scratch ----------------
__device__ float g_xm[B_ * N_ * C_ * T_];    // node-mixed x: [b][m][c][t]
__device__ float g_A[384 * 128];             // Weff: row kk = k*128 + c, col o (tf32-rounded)
__device__ float g_WcT[3 * 128 * 128];       // Wc transposed: [k][i][o]
__device__ float g_sfull[C_], g_s0[C_], g_sT[C_];
__device__ float g_tcs[C_], g_tcb[C_], g_bns[C_], g_bnb[C_], g_bconv[C_];
__device__ float g_rowsum[N_];

__device__ __forceinline__ uint32_t f2tf32(float f) {
    uint32_t r;
    asm("cvt.rna.tf32.f32 %0, %1;" : "=r"(r) : "f"(f));
    return r;
}

__device__ __forceinline__ void mma_tf32(float* d, const uint32_t* a, const uint32_t* b) {
    asm volatile(
        "mma.sync.aligned.m16n8k8.row.col.f32.tf32.tf32.f32 "
        "{%0,%1,%2,%3}, {%4,%5,%6,%7}, {%8,%9}, {%0,%1,%2,%3};"
        : "+f"(d[0]), "+f"(d[1]), "+f"(d[2]), "+f"(d[3])
        : "r"(a[0]), "r"(a[1]), "r"(a[2]), "r"(a[3]), "r"(b[0]), "r"(b[1]));
}

// ---------------- precompute stage 1: transpose Wc [o][i][k] -> [k][i][o] ----------------
__global__ void transpose_wc_kernel(const float* __restrict__ Wc)
{
    int idx = blockIdx.x * 256 + threadIdx.x;   // 3*128*128 = 49152
    if (idx < 3 * 128 * 128) {
        int o = idx & 127, i = (idx >> 7) & 127, k = idx >> 14;
        g_WcT[idx] = Wc[(o * 128 + i) * 3 + k];  // write coalesced (o fastest)
    }
}

// ---------------- precompute stage 2: Weff[k][c][o] = sum_i Wc[o,i,k] * Wg[i,c] ----------------
__global__ void precompute_w_kernel(const float* __restrict__ Wg)
{
    int k = blockIdx.x >> 3;
    int c0 = (blockIdx.x & 7) * 16;
    int o = threadIdx.x;  // 128 threads
    __shared__ float wgs[128][17];
    #pragma unroll
    for (int e = 0; e < 16; e++) {
        int idx = o + 128 * e;          // 0..2047
        int i = idx >> 4, j = idx & 15;
        wgs[i][j] = Wg[i * 128 + c0 + j];
    }
    __syncthreads();
    float acc[16];
    #pragma unroll
    for (int j = 0; j < 16; j++) acc[j] = 0.f;
    const float* wt = g_WcT + k * 16384 + o;
    #pragma unroll 4
    for (int i = 0; i < 128; i++) {
        float w = wt[i * 128];
        #pragma unroll
        for (int j = 0; j < 16; j++) acc[j] += w * wgs[i][j];
    }
    #pragma unroll
    for (int j = 0; j < 16; j++)
        g_A[(k * 128 + c0 + j) * 128 + o] = __uint_as_float(f2tf32(acc[j]));
}

// ---------------- precompute stage 3: biases / BN folds / adj row sums ----------------
__global__ void precompute_bias_kernel(
    const float* __restrict__ bg, const float* __restrict__ Wc,
    const float* __restrict__ bc,
    const float* __restrict__ tg, const float* __restrict__ tb,
    const float* __restrict__ tm, const float* __restrict__ tv,
    const float* __restrict__ bng, const float* __restrict__ bnbt,
    const float* __restrict__ bnm, const float* __restrict__ bnv,
    const float* __restrict__ adj)
{
    int o = threadIdx.x;  // 128
    float s0 = 0.f, s1 = 0.f, s2 = 0.f;
    for (int i = 0; i < C_; i++) {
        float b = bg[i];
        const float* w = &Wc[(o * C_ + i) * 3];
        s0 += w[0] * b; s1 += w[1] * b; s2 += w[2] * b;
    }
    g_sfull[o] = s0 + s1 + s2;
    g_s0[o] = s1 + s2;     // t==0: window misses k=0
    g_sT[o] = s0 + s1;     // t==T-1: window misses k=2
    g_bconv[o] = bc[o];
    float ts = tg[o] * rsqrtf(tv[o] + 1e-5f);
    g_tcs[o] = ts; g_tcb[o] = tb[o] - tm[o] * ts;
    float bs = bng[o] * rsqrtf(bnv[o] + 1e-5f);
    g_bns[o] = bs; g_bnb[o] = bnbt[o] - bnm[o] * bs;
    if (o < N_) {
        float r = 0.f;
        for (int n = 0; n < N_; n++) r += adj[o * N_ + n];
        g_rowsum[o] = r;
    }
}

// ---------------- kernel 2: node mix  xm[b,m,c,t] = sum_n adj[m,n] x[b,n,c,t] ----------------
__global__ __launch_bounds__(256) void mix_kernel(const float* __restrict__ x,
                                                  const float* __restrict__ adj)
{
    __shared__ float adjs[N_ * N_];
    int tid = threadIdx.x;
    for (int i = tid; i < N_ * N_; i += 256) adjs[i] = adj[i];
    __syncthreads();

    int b = blockIdx.y;
    int pos = blockIdx.x * 256 + tid;  // float4 index in [0, C*T/4)
    const float4* xb = (const float4*)x + (size_t)b * N_ * (C_ * T_ / 4) + pos;
    float4* xmb = (float4*)g_xm + (size_t)b * N_ * (C_ * T_ / 4) + pos;

    float4 acc[N_];
    #pragma unroll
    for (int m = 0; m < N_; m++) acc[m] = make_float4(0.f, 0.f, 0.f, 0.f);

    #pragma unroll 1
    for (int n = 0; n < N_; n++) {
        float4 v = xb[n * (C_ * T_ / 4)];
        #pragma unroll
        for (int m = 0; m < N_; m++) {
            float a = adjs[m * N_ + n];
            acc[m].x += a * v.x; acc[m].y += a * v.y;
            acc[m].z += a * v.z; acc[m].w += a * v.w;
        }
    }
    #pragma unroll
    for (int m = 0; m < N_; m++) xmb[m * (C_ * T_ / 4)] = acc[m];
}

// ---------------- kernel 3: tf32 mma.sync conv-GEMM + full epilogue ----------------
// y[o, t] = sum_{k,c} Weff[k][c][o] * xm[c, t+k-1]   (M=128 t, N=128 o, K=384)
// Inner loop identical to the measured-432us R3 kernel; epilogue fused.
#define XS_STRIDE 136
#define GEMM_SMEM (64 * 130 * 4)   // 33280 B: Ds[64][130]; xs[32][136] aliases front

__global__ __launch_bounds__(256) void stgemm_kernel(const float* __restrict__ x,
                                                     float* __restrict__ out)
{
    extern __shared__ float smemf[];
    float* xs = smemf;              // [32][136]; col 3 = t0-1, 4..131 = t0..t0+127, 132 = t0+128
    float* Ds = smemf;              // [64][130] (epilogue reuse)

    int tid = threadIdx.x, lane = tid & 31, wid = tid >> 5;
    int wm = wid >> 2, wn = wid & 3;
    int t0 = blockIdx.x * 128;
    int m_node = blockIdx.y;
    int node = blockIdx.z * N_ + m_node;
    const float* xp = g_xm + (size_t)node * C_ * T_;

    float d[4][4][4];
    #pragma unroll
    for (int mt = 0; mt < 4; mt++)
        #pragma unroll
        for (int nt = 0; nt < 4; nt++)
            #pragma unroll
            for (int r = 0; r < 4; r++) d[mt][nt][r] = 0.f;

    const float* xsb = xs + (lane & 3) * XS_STRIDE + wm * 64 + (lane >> 2) + 3;
    const float* gAb = g_A + (lane & 3) * 128 + wn * 32 + (lane >> 2);

    #pragma unroll 1
    for (int cc = 0; cc < 4; cc++) {
        int c0 = cc * 32;
        __syncthreads();
        // stage xm rows [c0..c0+32) x t window [t0-1, t0+128], tf32-rounded
        #pragma unroll
        for (int e = 0; e < 4; e++) {
            int idx = tid + 256 * e;               // 0..1023
            int ci = idx >> 5, tq = idx & 31;
            float4 v = *(const float4*)&xp[(c0 + ci) * T_ + t0 + 4 * tq];
            v.x = __uint_as_float(f2tf32(v.x));
            v.y = __uint_as_float(f2tf32(v.y));
            v.z = __uint_as_float(f2tf32(v.z));
            v.w = __uint_as_float(f2tf32(v.w));
            *(float4*)&xs[ci * XS_STRIDE + 4 + 4 * tq] = v;
        }
        if (tid < 32) {
            xs[tid * XS_STRIDE + 3] =
                (t0 > 0) ? __uint_as_float(f2tf32(xp[(c0 + tid) * T_ + t0 - 1])) : 0.f;
        } else if (tid < 64) {
            int ci = tid - 32;
            xs[ci * XS_STRIDE + 132] =
                (t0 + 128 < T_) ? __uint_as_float(f2tf32(xp[(c0 + ci) * T_ + t0 + 128])) : 0.f;
        }
        __syncthreads();

        #pragma unroll
        for (int k = 0; k < 3; k++) {
            int kk0 = k * 128 + c0;
            #pragma unroll
            for (int ks = 0; ks < 4; ks++) {
                int cl = 8 * ks;
                // B fragments straight from L2-resident g_A
                uint32_t b[4][2];
                const float* gp = gAb + (kk0 + cl) * 128;
                #pragma unroll
                for (int nt = 0; nt < 4; nt++) {
                    b[nt][0] = __float_as_uint(gp[8 * nt]);
                    b[nt][1] = __float_as_uint(gp[4 * 128 + 8 * nt]);
                }
                // A fragments from smem (conflict-free)
                const float* xq = xsb + cl * XS_STRIDE + k;
                #pragma unroll
                for (int mt = 0; mt < 4; mt++) {
                    uint32_t a[4];
                    a[0] = __float_as_uint(xq[mt * 16]);
                    a[1] = __float_as_uint(xq[mt * 16 + 8]);
                    a[2] = __float_as_uint(xq[4 * XS_STRIDE + mt * 16]);
                    a[3] = __float_as_uint(xq[4 * XS_STRIDE + mt * 16 + 8]);
                    #pragma unroll
                    for (int nt = 0; nt < 4; nt++) mma_tf32(d[mt][nt], a, b[nt]);
                }
            }
        }
    }

    // ---- epilogue: transpose through smem + bias/BN/relu/residual, coalesced out ----
    const float* xr = x + (size_t)node * C_ * T_;
    float* yo = out + (size_t)node * C_ * T_;
    float rs = g_rowsum[m_node];

    #pragma unroll 1
    for (int p = 0; p < 2; p++) {
        __syncthreads();
        if (wm == p) {
            #pragma unroll
            for (int mt = 0; mt < 4; mt++) {
                int r = mt * 16 + (lane >> 2);
                #pragma unroll
                for (int nt = 0; nt < 4; nt++) {
                    int cl = wn * 32 + nt * 8 + 2 * (lane & 3);
                    *(float2*)&Ds[r * 130 + cl]       = make_float2(d[mt][nt][0], d[mt][nt][1]);
                    *(float2*)&Ds[(r + 8) * 130 + cl] = make_float2(d[mt][nt][2], d[mt][nt][3]);
                }
            }
        }
        __syncthreads();
        #pragma unroll
        for (int i = 0; i < 32; i++) {
            int idx = tid + 256 * i;       // 0..8191
            int o = idx >> 6, tt = idx & 63;
            int t = t0 + p * 64 + tt;
            float v = Ds[tt * 130 + o];
            float sv = g_sfull[o];
            if (t == 0) sv = g_s0[o];
            else if (t == T_ - 1) sv = g_sT[o];
            float bias = g_bconv[o] + rs * sv;
            float p1 = v + bias;
            float y1 = fmaxf(g_tcs[o] * p1 + g_tcb[o], 0.f);
            float y2 = y1 + xr[o * T_ + t];
            yo[o * T_ + t] = fmaxf(g_bns[o] * y2 + g_bnb[o], 0.f);
        }
    }
}

// ---------------- launch ----------------
extern "C" void kernel_launch(void* const* d_in, const int* in_sizes, int n_in,
                              void* d_out, int out_size)
{
    const float* x   = (const float*)d_in[0];
    const float* adj = (const float*)d_in[1];
    const float* Wg  = (const float*)d_in[2];
    const float* bg  = (const float*)d_in[3];
    const float* Wc  = (const float*)d_in[4];
    const float* bc  = (const float*)d_in[5];
    const float* tg  = (const float*)d_in[6];
    const float* tb  = (const float*)d_in[7];
    const float* tm  = (const float*)d_in[8];
    const float* tv  = (const float*)d_in[9];
    const float* bng = (const float*)d_in[10];
    const float* bnb = (const float*)d_in[11];
    const float* bnm = (const float*)d_in[12];
    const float* bnv = (const float*)d_in[13];

    transpose_wc_kernel<<<192, 256>>>(Wc);
    precompute_w_kernel<<<24, 128>>>(Wg);
    precompute_bias_kernel<<<1, 128>>>(bg, Wc, bc, tg, tb, tm, tv, bng, bnb, bnm, bnv, adj);
    mix_kernel<<<dim3(C_ * T_ / 4 / 256, B_), 256>>>(x, adj);
    stgemm_kernel<<<dim3(2, N_, B_), 256, GEMM_SMEM>>>(x, (float*)d_out);
}

// round 9
// speedup vs baseline: 2.2272x; 2.2078x over previous
#include <cuda_runtime.h>
#include <cstdint>

#define B_ 64
#define N_ 25
#define C_ 128
#define T_ 256

// ---------------- device scratch ----------------
__device__ float g_z[B_ * N_ * C_ * T_];           // GEMM output per node (pre-mix) [b][n][o][t]
__device__ float g_Bf[3 * 4 * 4 * 2 * 4 * 32 * 4]; // Weff frag order [k][cc][ks][half][wn][lane][4]
__device__ float g_WcT[3 * 128 * 128];             // Wc transposed: [k][i][o]
__device__ float g_sfull[C_], g_s0[C_], g_sT[C_];
__device__ float g_tcs[C_], g_tcb[C_], g_bns[C_], g_bnb[C_], g_bconv[C_];
__device__ float g_rowsum[N_];

__device__ __forceinline__ uint32_t f2tf32(float f) {
    uint32_t r;
    asm("cvt.rna.tf32.f32 %0, %1;" : "=r"(r) : "f"(f));
    return r;
}

__device__ __forceinline__ void mma_tf32(float* d, const uint32_t* a, uint32_t b0, uint32_t b1) {
    asm volatile(
        "mma.sync.aligned.m16n8k8.row.col.f32.tf32.tf32.f32 "
        "{%0,%1,%2,%3}, {%4,%5,%6,%7}, {%8,%9}, {%0,%1,%2,%3};"
        : "+f"(d[0]), "+f"(d[1]), "+f"(d[2]), "+f"(d[3])
        : "r"(a[0]), "r"(a[1]), "r"(a[2]), "r"(a[3]), "r"(b0), "r"(b1));
}

// ---------------- precompute stage 1: transpose Wc [o][i][k] -> [k][i][o] ----------------
__global__ void transpose_wc_kernel(const float* __restrict__ Wc)
{
    int idx = blockIdx.x * 256 + threadIdx.x;   // 3*128*128 = 49152
    if (idx < 3 * 128 * 128) {
        int o = idx & 127, i = (idx >> 7) & 127, k = idx >> 14;
        g_WcT[idx] = Wc[(o * 128 + i) * 3 + k];  // write coalesced (o fastest)
    }
}

// ---------------- precompute stage 2: Weff[k][c][o] -> fragment layout g_Bf ----------------
// Verified mapping (R6, same rel_err as row layout): for element (o, c):
// wn=o>>5, nt=(o&31)>>3, lane=((o&7)<<2)|(c&3), half=nt>>1, j4=((nt&1)<<1)|((c>>2)&1)
__global__ void precompute_w_kernel(const float* __restrict__ Wg)
{
    int k = blockIdx.x >> 3;
    int c0 = (blockIdx.x & 7) * 16;
    int o = threadIdx.x;  // 128 threads
    __shared__ float wgs[128][17];
    #pragma unroll
    for (int e = 0; e < 16; e++) {
        int idx = o + 128 * e;          // 0..2047
        int i = idx >> 4, j = idx & 15;
        wgs[i][j] = Wg[i * 128 + c0 + j];
    }
    __syncthreads();
    float acc[16];
    #pragma unroll
    for (int j = 0; j < 16; j++) acc[j] = 0.f;
    const float* wt = g_WcT + k * 16384 + o;
    #pragma unroll 4
    for (int i = 0; i < 128; i++) {
        float w = wt[i * 128];
        #pragma unroll
        for (int j = 0; j < 16; j++) acc[j] += w * wgs[i][j];
    }
    int wn = o >> 5, s = o & 31;
    int l2 = s & 7, nt = s >> 3, half = nt >> 1, ntl = nt & 1;
    #pragma unroll
    for (int jj = 0; jj < 16; jj++) {
        int c = c0 + jj;
        int cc = c >> 5, r = c & 31;
        int ks = r >> 3, q = r & 7;
        int lj = q & 3, j = q >> 2;
        int lane = (l2 << 2) | lj;
        int j4 = (ntl << 1) | j;
        size_t idx = ((size_t)(((((k * 4 + cc) * 4 + ks) * 2 + half) * 4 + wn) * 32 + lane) << 2) + j4;
        g_Bf[idx] = __uint_as_float(f2tf32(acc[jj]));
    }
}

// ---------------- precompute stage 3: biases / BN folds / adj row sums ----------------
__global__ void precompute_bias_kernel(
    const float* __restrict__ bg, const float* __restrict__ Wc,
    const float* __restrict__ bc,
    const float* __restrict__ tg, const float* __restrict__ tb,
    const float* __restrict__ tm, const float* __restrict__ tv,
    const float* __restrict__ bng, const float* __restrict__ bnbt,
    const float* __restrict__ bnm, const float* __restrict__ bnv,
    const float* __restrict__ adj)
{
    int o = threadIdx.x;  // 128
    float s0 = 0.f, s1 = 0.f, s2 = 0.f;
    for (int i = 0; i < C_; i++) {
        float b = bg[i];
        const float* w = &Wc[(o * C_ + i) * 3];
        s0 += w[0] * b; s1 += w[1] * b; s2 += w[2] * b;
    }
    g_sfull[o] = s0 + s1 + s2;
    g_s0[o] = s1 + s2;     // t==0: window misses k=0
    g_sT[o] = s0 + s1;     // t==T-1: window misses k=2
    g_bconv[o] = bc[o];
    float ts = tg[o] * rsqrtf(tv[o] + 1e-5f);
    g_tcs[o] = ts; g_tcb[o] = tb[o] - tm[o] * ts;
    float bs = bng[o] * rsqrtf(bnv[o] + 1e-5f);
    g_bns[o] = bs; g_bnb[o] = bnbt[o] - bnm[o] * bs;
    if (o < N_) {
        float r = 0.f;
        for (int n = 0; n < N_; n++) r += adj[o * N_ + n];
        g_rowsum[o] = r;
    }
}

// ---------------- kernel 2: tf32 mma.sync conv-GEMM per (b, n, t-half) ----------------
// z[o, t] = sum_{k,c} Weff[k][c][o] * x[c, t+k-1]   (M=128 t, N=128 o, K=384)
// R3 structure verbatim; ONLY change: B frags via 2 warp-contiguous LDG.128 from g_Bf.
#define XS_STRIDE 136
#define GEMM_SMEM (64 * 130 * 4)   // 33280 B: Ds[64][130]; xs[32][136] aliases front

__global__ __launch_bounds__(256) void stgemm_kernel(const float* __restrict__ x)
{
    extern __shared__ float smemf[];
    float* xs = smemf;              // [32][136]; col 3 = t0-1, 4..131 = t0..t0+127, 132 = t0+128
    float* Ds = smemf;              // [64][130] (epilogue reuse)

    int tid = threadIdx.x, lane = tid & 31, wid = tid >> 5;
    int wm = wid >> 2, wn = wid & 3;
    int t0 = blockIdx.x * 128;
    int node = blockIdx.z * N_ + blockIdx.y;
    const float* xp = x + (size_t)node * C_ * T_;

    float d[4][4][4];
    #pragma unroll
    for (int mt = 0; mt < 4; mt++)
        #pragma unroll
        for (int nt = 0; nt < 4; nt++)
            #pragma unroll
            for (int r = 0; r < 4; r++) d[mt][nt][r] = 0.f;

    const float* xsb = xs + (lane & 3) * XS_STRIDE + wm * 64 + (lane >> 2) + 3;
    const float4* gB4 = (const float4*)g_Bf;   // [((fb)*4+wn)*32+lane]

    #pragma unroll 1
    for (int cc = 0; cc < 4; cc++) {
        int c0 = cc * 32;
        __syncthreads();
        // stage x rows [c0..c0+32) x t window [t0-1, t0+128], tf32-rounded
        #pragma unroll
        for (int e = 0; e < 4; e++) {
            int idx = tid + 256 * e;               // 0..1023
            int ci = idx >> 5, tq = idx & 31;
            float4 v = *(const float4*)&xp[(c0 + ci) * T_ + t0 + 4 * tq];
            v.x = __uint_as_float(f2tf32(v.x));
            v.y = __uint_as_float(f2tf32(v.y));
            v.z = __uint_as_float(f2tf32(v.z));
            v.w = __uint_as_float(f2tf32(v.w));
            *(float4*)&xs[ci * XS_STRIDE + 4 + 4 * tq] = v;
        }
        if (tid < 32) {
            xs[tid * XS_STRIDE + 3] =
                (t0 > 0) ? __uint_as_float(f2tf32(xp[(c0 + tid) * T_ + t0 - 1])) : 0.f;
        } else if (tid < 64) {
            int ci = tid - 32;
            xs[ci * XS_STRIDE + 132] =
                (t0 + 128 < T_) ? __uint_as_float(f2tf32(xp[(c0 + ci) * T_ + t0 + 128])) : 0.f;
        }
        __syncthreads();

        #pragma unroll 1
        for (int k = 0; k < 3; k++) {
            #pragma unroll
            for (int ks = 0; ks < 4; ks++) {
                // B frags: two warp-contiguous LDG.128 from fragment-ordered g_Bf
                int fb = ((k * 4 + cc) * 4 + ks) * 2;
                float4 v0 = gB4[((fb + 0) * 4 + wn) * 32 + lane];
                float4 v1 = gB4[((fb + 1) * 4 + wn) * 32 + lane];
                uint32_t bb[8];
                bb[0] = __float_as_uint(v0.x); bb[1] = __float_as_uint(v0.y);
                bb[2] = __float_as_uint(v0.z); bb[3] = __float_as_uint(v0.w);
                bb[4] = __float_as_uint(v1.x); bb[5] = __float_as_uint(v1.y);
                bb[6] = __float_as_uint(v1.z); bb[7] = __float_as_uint(v1.w);

                // A fragments from smem (conflict-free)
                const float* xq = xsb + 8 * ks * XS_STRIDE + k;
                #pragma unroll
                for (int mt = 0; mt < 4; mt++) {
                    uint32_t a[4];
                    a[0] = __float_as_uint(xq[mt * 16]);
                    a[1] = __float_as_uint(xq[mt * 16 + 8]);
                    a[2] = __float_as_uint(xq[4 * XS_STRIDE + mt * 16]);
                    a[3] = __float_as_uint(xq[4 * XS_STRIDE + mt * 16 + 8]);
                    #pragma unroll
                    for (int nt = 0; nt < 4; nt++)
                        mma_tf32(d[mt][nt], a, bb[2 * nt], bb[2 * nt + 1]);
                }
            }
        }
    }

    // ---- epilogue: transpose through smem, coalesced store to g_z[o][t] ----
    float* zp = g_z + (size_t)node * C_ * T_;
    #pragma unroll 1
    for (int p = 0; p < 2; p++) {
        __syncthreads();
        if (wm == p) {
            #pragma unroll
            for (int mt = 0; mt < 4; mt++) {
                int r = mt * 16 + (lane >> 2);
                #pragma unroll
                for (int nt = 0; nt < 4; nt++) {
                    int cl = wn * 32 + nt * 8 + 2 * (lane & 3);
                    *(float2*)&Ds[r * 130 + cl]       = make_float2(d[mt][nt][0], d[mt][nt][1]);
                    *(float2*)&Ds[(r + 8) * 130 + cl] = make_float2(d[mt][nt][2], d[mt][nt][3]);
                }
            }
        }
        __syncthreads();
        #pragma unroll
        for (int i = 0; i < 32; i++) {
            int idx = tid + 256 * i;       // 0..8191
            int o = idx >> 6, tt = idx & 63;
            zp[o * T_ + t0 + p * 64 + tt] = Ds[tt * 130 + o];
        }
    }
}

// ---------------- kernel 3: fused node-mix + full epilogue (R3 verbatim) ----------------
__global__ __launch_bounds__(256) void fuse_kernel(const float* __restrict__ x,
                                                   const float* __restrict__ adj,
                                                   float* __restrict__ out)
{
    __shared__ float adjs[N_ * N_];
    int tid = threadIdx.x;
    for (int i = tid; i < N_ * N_; i += 256) adjs[i] = adj[i];
    __syncthreads();

    int b = blockIdx.y;
    int pos = blockIdx.x * 256 + tid;       // float4 index in [0, C*T/4)
    int o = pos >> 6;
    int tbase = 4 * (pos & 63);

    const float4* zb = (const float4*)g_z + (size_t)b * N_ * (C_ * T_ / 4) + pos;
    const float4* xb = (const float4*)x + (size_t)b * N_ * (C_ * T_ / 4) + pos;
    float4* ob_ = (float4*)out + (size_t)b * N_ * (C_ * T_ / 4) + pos;

    float4 acc[N_];
    #pragma unroll
    for (int m = 0; m < N_; m++) acc[m] = make_float4(0.f, 0.f, 0.f, 0.f);

    #pragma unroll 1
    for (int n = 0; n < N_; n++) {
        float4 v = zb[n * (C_ * T_ / 4)];
        #pragma unroll
        for (int m = 0; m < N_; m++) {
            float a = adjs[m * N_ + n];
            acc[m].x += a * v.x; acc[m].y += a * v.y;
            acc[m].z += a * v.z; acc[m].w += a * v.w;
        }
    }

    float sfull = g_sfull[o], s0v = g_s0[o], sTv = g_sT[o], bcv = g_bconv[o];
    float tcs = g_tcs[o], tcb = g_tcb[o], bns = g_bns[o], bnb = g_bnb[o];
    bool e0 = (tbase == 0), eT = (tbase + 3 == T_ - 1);

    #pragma unroll 1
    for (int m = 0; m < N_; m++) {
        float rs = g_rowsum[m];
        float bias_f = bcv + rs * sfull;
        float v[4] = { acc[m].x, acc[m].y, acc[m].z, acc[m].w };
        float bias[4] = { bias_f, bias_f, bias_f, bias_f };
        if (e0) bias[0] = bcv + rs * s0v;
        if (eT) bias[3] = bcv + rs * sTv;
        float4 r = xb[m * (C_ * T_ / 4)];
        float res[4] = { r.x, r.y, r.z, r.w };
        float ov[4];
        #pragma unroll
        for (int j = 0; j < 4; j++) {
            float p = v[j] + bias[j];
            float y1 = fmaxf(tcs * p + tcb, 0.f);
            float y2 = y1 + res[j];
            ov[j] = fmaxf(bns * y2 + bnb, 0.f);
        }
        ob_[m * (C_ * T_ / 4)] = make_float4(ov[0], ov[1], ov[2], ov[3]);
    }
}

// ---------------- launch ----------------
extern "C" void kernel_launch(void* const* d_in, const int* in_sizes, int n_in,
                              void* d_out, int out_size)
{
    const float* x   = (const float*)d_in[0];
    const float* adj = (const float*)d_in[1];
    const float* Wg  = (const float*)d_in[2];
    const float* bg  = (const float*)d_in[3];
    const float* Wc  = (const float*)d_in[4];
    const float* bc  = (const float*)d_in[5];
    const float* tg  = (const float*)d_in[6];
    const float* tb  = (const float*)d_in[7];
    const float* tm  = (const float*)d_in[8];
    const float* tv  = (const float*)d_in[9];
    const float* bng = (const float*)d_in[10];
    const float* bnb = (const float*)d_in[11];
    const float* bnm = (const float*)d_in[12];
    const float* bnv = (const float*)d_in[13];

    transpose_wc_kernel<<<192, 256>>>(Wc);
    precompute_w_kernel<<<24, 128>>>(Wg);
    precompute_bias_kernel<<<1, 128>>>(bg, Wc, bc, tg, tb, tm, tv, bng, bnb, bnm, bnv, adj);
    stgemm_kernel<<<dim3(2, N_, B_), 256, GEMM_SMEM>>>(x);
    fuse_kernel<<<dim3(C_ * T_ / 4 / 256, B_), 256>>>(x, adj, (float*)d_out);
}